// round 10
// baseline (speedup 1.0000x reference)
#include <cuda_runtime.h>
#include <math_constants.h>

#define BB 64
#define JJ 32
#define MM 160
#define NN 160
#define HW (MM * NN)     // 25600
#define NV4 (HW / 4)     // 6400 float4 per row
#define THREADS 256
#define NWARP (THREADS / 32)   // 8
#define NOBJ (BB * JJ)   // 2048
#define GRID 608         // ~4 CTAs/SM, single wave; ticket self-balances
#define PERIOD ((unsigned long long)(NOBJ + GRID))  // work + exit slots per launch

__device__ float g_perobj[NOBJ];
__device__ unsigned long long g_ticket = 0;  // monotone across replays
__device__ unsigned long long g_count  = 0;  // monotone across replays

// Persistent CTAs pull rows from a ticket counter: SM-level load balancing
// (near/far-die, 13-vs-14-row quantization) happens automatically.
// Epoch trick: each launch consumes exactly PERIOD tickets (2048 work grabs +
// one exit grab per CTA), so `ticket % PERIOD` is replay-deterministic with
// no counter reset and no extra graph node.
__global__ __launch_bounds__(THREADS, 4) void argmax_loss_persistent_kernel(
    const float* __restrict__ pred,
    const float* __restrict__ gt,
    const float* __restrict__ heatmap,
    float* __restrict__ out)
{
    const int tid  = threadIdx.x;
    const int warp = tid >> 5;
    const int lane = tid & 31;

    __shared__ int   s_row;
    __shared__ float svals[NWARP];
    __shared__ int   sidx[NWARP];

    for (;;) {
        if (tid == 0) {
            unsigned long long t = atomicAdd(&g_ticket, 1ull);
            s_row = (int)(t % PERIOD);
        }
        __syncthreads();
        const int bj = s_row;
        if (bj >= NOBJ) return;    // exit slot: this CTA is done

        const float4* row = reinterpret_cast<const float4*>(heatmap + (size_t)bj * HW);

        // Per-thread scan: 6400/256 = 25 float4. fmax-tree body (3 FMNMX),
        // one predicated (best, i) update per float4; strict > keeps the
        // earliest float4 on ties.
        float best = -CUDART_INF_F;
        int   bi   = 0;
        #pragma unroll 5
        for (int i = tid; i < NV4; i += THREADS) {
            float4 v = row[i];
            float m = fmaxf(fmaxf(v.x, v.y), fmaxf(v.z, v.w));
            if (m > best) { best = m; bi = i; }
        }

        // Resolve element within the winning float4 (first equal wins;
        // fmaxf returns operand bits exactly, so == matches).
        int bidx;
        {
            float4 v = row[bi];
            int e = 3;
            if (v.z == best) e = 2;
            if (v.y == best) e = 1;
            if (v.x == best) e = 0;
            bidx = bi * 4 + e;
        }

        // Warp-level (val, idx) reduction, first-index tie-break.
        #pragma unroll
        for (int off = 16; off > 0; off >>= 1) {
            float ov = __shfl_down_sync(0xFFFFFFFFu, best, off);
            int   oi = __shfl_down_sync(0xFFFFFFFFu, bidx, off);
            if (ov > best || (ov == best && oi < bidx)) { best = ov; bidx = oi; }
        }
        if (lane == 0) { svals[warp] = best; sidx[warp] = bidx; }
        __syncthreads();
        // Warps 1..7 loop back to the ticket barrier; svals/sidx for the next
        // row are only written after warp 0 (which reads them below) arrives
        // at that barrier, so there is no overwrite race.

        if (warp == 0) {
            // Merge 8 warp winners in-warp (lanes 0..7 hold candidates).
            float mv = (lane < NWARP) ? svals[lane] : -CUDART_INF_F;
            int   mi = (lane < NWARP) ? sidx[lane]  : 0x7FFFFFFF;
            #pragma unroll
            for (int off = 4; off > 0; off >>= 1) {
                float ov = __shfl_down_sync(0xFFFFFFFFu, mv, off);
                int   oi = __shfl_down_sync(0xFFFFFFFFu, mi, off);
                if (ov > mv || (ov == mv && oi < mi)) { mv = ov; mi = oi; }
            }

            unsigned long long cnt = 0;
            if (lane == 0) {
                int idx = mi;
                float x = (float)(idx / MM);   // reference: idx // m
                float y = (float)(idx % MM);   // reference: idx %  m

                int b = bj / JJ;
                int j = bj % JJ;

                const float* g = gt + ((size_t)b * JJ + j) * 11;
                float g7 = g[7], g8 = g[8], g9 = g[9], g10 = g[10];
                bool valid = (g9 > 0.0f) && (g10 > 0.0f) &&
                             (g9 < (float)MM) && (g10 < (float)NN);

                // pred layout: (B, 9, J, 1) -> pred[((b*9 + c)*J) + j]
                const float* pb = pred + (size_t)b * 9 * JJ + j;
                float px = pb[7 * JJ];
                float py = pb[8 * JJ];

                float dx = g9 + g7 - x - px;
                float dy = g10 + g8 - y - py;
                float loss = dx * dx + dy * dy;

                float cls = 0.0f;
                #pragma unroll
                for (int c = 0; c < 7; c++) {
                    float d = pb[c * JJ] - g[c];
                    cls = fmaf(d, d, cls);
                }

                g_perobj[bj] = valid ? (cls + loss) : 0.0f;

                // Release-add: orders the g_perobj store before the count
                // bump without a per-row L1-flushing __threadfence().
                asm volatile("atom.release.gpu.add.u64 %0, [%1], 1;"
                             : "=l"(cnt) : "l"(&g_count) : "memory");
            }
            cnt = __shfl_sync(0xFFFFFFFFu, cnt, 0);

            if ((unsigned int)(cnt % (unsigned long long)NOBJ) == NOBJ - 1) {
                // Last row of this launch: acquire side, then final 2048->64.
                __threadfence();
                #pragma unroll
                for (int r = 0; r < 2; r++) {
                    int b = lane * 2 + r;
                    float s = 0.0f;
                    #pragma unroll
                    for (int j = 0; j < JJ; j++)
                        s += __ldcg(&g_perobj[b * JJ + j]);
                    out[b] = s;
                }
            }
        }
    }
}

extern "C" void kernel_launch(void* const* d_in, const int* in_sizes, int n_in,
                              void* d_out, int out_size)
{
    const float* pred    = (const float*)d_in[0];
    const float* gt      = (const float*)d_in[1];
    const float* heatmap = (const float*)d_in[2];
    float* out = (float*)d_out;

    argmax_loss_persistent_kernel<<<GRID, THREADS>>>(pred, gt, heatmap, out);
}

// round 11
// speedup vs baseline: 1.0494x; 1.0494x over previous
#include <cuda_runtime.h>
#include <math_constants.h>

#define BB 64
#define JJ 32
#define MM 160
#define NN 160
#define HW (MM * NN)       // 25600
#define NV4 (HW / 4)       // 6400 float4 per row
#define SEG 2              // blocks per row
#define SEGV4 (NV4 / SEG)  // 3200 float4 per segment
#define THREADS 128
#define NWARP (THREADS / 32)
#define NOBJ (BB * JJ)     // 2048
#define TOTBLK (NOBJ * SEG)

// g_best starts zeroed (module init) and is re-zeroed by the last finisher
// each launch. Encoded keys are always > 0 for finite floats, so 0 == empty.
__device__ unsigned long long g_best[NOBJ];
__device__ float g_perobj[NOBJ];
__device__ unsigned int g_rowdone[NOBJ];      // monotone: +SEG per launch
__device__ unsigned long long g_done = 0;     // monotone: +NOBJ per launch

// Monotone order-preserving float->u32 (sign-flip trick).
__device__ __forceinline__ unsigned int enc_f32(float f) {
    unsigned int u = __float_as_uint(f);
    return (u & 0x80000000u) ? ~u : (u | 0x80000000u);
}

__global__ __launch_bounds__(THREADS, 16) void argmax_loss_seg_kernel(
    const float* __restrict__ pred,
    const float* __restrict__ gt,
    const float* __restrict__ heatmap,
    float* __restrict__ out)
{
    const int blk = blockIdx.x;
    const int row = blk >> 1;          // 0 .. 2047
    const int seg = blk & 1;
    const int tid = threadIdx.x;
    const int warp = tid >> 5;
    const int lane = tid & 31;

    const float4* rp = reinterpret_cast<const float4*>(heatmap + (size_t)row * HW);

    // Scan this block's half-row: 3200/128 = 25 float4 per thread.
    float best = -CUDART_INF_F;
    int   bi   = seg * SEGV4 + tid;
    #pragma unroll 5
    for (int i = seg * SEGV4 + tid; i < (seg + 1) * SEGV4; i += THREADS) {
        float4 v = rp[i];
        float m = fmaxf(fmaxf(v.x, v.y), fmaxf(v.z, v.w));
        if (m > best) { best = m; bi = i; }   // strict > keeps earliest float4
    }

    // Resolve element within winning float4 (first equal wins; fmaxf is bit-exact).
    int bidx;
    {
        float4 v = rp[bi];
        int e = 3;
        if (v.z == best) e = 2;
        if (v.y == best) e = 1;
        if (v.x == best) e = 0;
        bidx = bi * 4 + e;
    }

    // Warp (val, idx) reduction, first-index tie-break.
    #pragma unroll
    for (int off = 16; off > 0; off >>= 1) {
        float ov = __shfl_down_sync(0xFFFFFFFFu, best, off);
        int   oi = __shfl_down_sync(0xFFFFFFFFu, bidx, off);
        if (ov > best || (ov == best && oi < bidx)) { best = ov; bidx = oi; }
    }

    __shared__ float svals[NWARP];
    __shared__ int   sidx[NWARP];
    __shared__ int   s_flag;   // 0 = exit, 1 = this block does the final pass
    if (lane == 0) { svals[warp] = best; sidx[warp] = bidx; }
    __syncthreads();

    if (warp == 0) {
        // Merge 4 warp winners (lanes 0..3 hold candidates).
        float mv = (lane < NWARP) ? svals[lane] : -CUDART_INF_F;
        int   mi = (lane < NWARP) ? sidx[lane]  : 0x7FFFFFFF;
        #pragma unroll
        for (int off = 2; off > 0; off >>= 1) {
            float ov = __shfl_down_sync(0xFFFFFFFFu, mv, off);
            int   oi = __shfl_down_sync(0xFFFFFFFFu, mi, off);
            if (ov > mv || (ov == mv && oi < mi)) { mv = ov; mi = oi; }
        }

        if (lane == 0) {
            int flag = 0;
            // Encoded key: bigger value wins; tie -> bigger (~idx) -> smaller idx.
            unsigned long long key =
                ((unsigned long long)enc_f32(mv) << 32) |
                (unsigned long long)(0xFFFFFFFFu - (unsigned int)mi);
            atomicMax(&g_best[row], key);

            // Per-row finish counter (monotone, +2 per launch). acq_rel:
            // release my atomicMax, acquire the peer's if I'm second.
            unsigned int rc;
            asm volatile("atom.acq_rel.gpu.add.u32 %0, [%1], 1;"
                         : "=r"(rc) : "l"(&g_rowdone[row]) : "memory");

            if ((rc & 1u) == 1u) {     // second block of this row this launch
                unsigned long long k = __ldcg(&g_best[row]);
                int idx = (int)(0xFFFFFFFFu - (unsigned int)(k & 0xFFFFFFFFull));

                float x = (float)(idx / MM);   // reference: idx // m
                float y = (float)(idx % MM);   // reference: idx %  m

                int b = row / JJ;
                int j = row % JJ;

                const float* g = gt + ((size_t)b * JJ + j) * 11;
                float g7 = g[7], g8 = g[8], g9 = g[9], g10 = g[10];
                bool valid = (g9 > 0.0f) && (g10 > 0.0f) &&
                             (g9 < (float)MM) && (g10 < (float)NN);

                // pred layout: (B, 9, J, 1) -> pred[((b*9 + c)*J) + j]
                const float* pb = pred + (size_t)b * 9 * JJ + j;
                float px = pb[7 * JJ];
                float py = pb[8 * JJ];

                float dx = g9 + g7 - x - px;
                float dy = g10 + g8 - y - py;
                float loss = dx * dx + dy * dy;

                float cls = 0.0f;
                #pragma unroll
                for (int c = 0; c < 7; c++) {
                    float d = pb[c * JJ] - g[c];
                    cls = fmaf(d, d, cls);
                }

                g_perobj[row] = valid ? (cls + loss) : 0.0f;

                // Global row-finish counter (monotone, +NOBJ per launch).
                unsigned long long cnt;
                asm volatile("atom.release.gpu.add.u64 %0, [%1], 1;"
                             : "=l"(cnt) : "l"(&g_done) : "memory");
                if ((unsigned int)(cnt % (unsigned long long)NOBJ) == NOBJ - 1)
                    flag = 1;
            }
            s_flag = flag;
        }
    }
    __syncthreads();

    if (s_flag) {
        // Last finisher block: acquire, 2048 -> 64 sum, reset g_best.
        __threadfence();
        if (tid < BB) {
            float s = 0.0f;
            #pragma unroll
            for (int j = 0; j < JJ; j++)
                s += __ldcg(&g_perobj[tid * JJ + j]);
            out[tid] = s;
        }
        // Re-zero keys for the next launch (graph replay determinism).
        for (int o = tid; o < NOBJ; o += THREADS)
            g_best[o] = 0ull;
    }
}

extern "C" void kernel_launch(void* const* d_in, const int* in_sizes, int n_in,
                              void* d_out, int out_size)
{
    const float* pred    = (const float*)d_in[0];
    const float* gt      = (const float*)d_in[1];
    const float* heatmap = (const float*)d_in[2];
    float* out = (float*)d_out;

    argmax_loss_seg_kernel<<<TOTBLK, THREADS>>>(pred, gt, heatmap, out);
}